// round 14
// baseline (speedup 1.0000x reference)
#include <cuda_runtime.h>
#include <cuda_fp16.h>
#include <cstdint>
#include <cmath>

// ============================================================================
// out[m,n] = sum_k sign(x[m,k]) * sign(w[n,k]-th[n]) * 2^round(clip(shift,-8,0))
//   M = 8192, N = 16384, K = 4096, out fp32.
// sm_103 legacy tensor path (no tcgen05 on non-'a' target).
// R12/R13: bf16/f16 HMMA m16n8k16 uniformly rate-capped (rt~8/SMSP) -> 1.9ms floor.
// This round: legacy FP8 MMA, 2x MAC per instruction at (hopefully) same rate:
//   mma.sync.aligned.m16n8k32.row.col.f32.e4m3.e4m3.f32
// +/-1 exact in e4m3 (0x38/0xB8), f32 accumulation exact -> bit-exact result.
// Fragment byte-layout identical to R7's PASSED s8 m16n8k32 kernel.
// ============================================================================

#define BM   8192
#define NNN  16384
#define KKK  4096
#define TILE_M 128
#define TILE_N 256
#define NKC  (KKK / 128)          // 32 k-chunks of 128 fp8 (=128B SW128 row)
#define STAGES 4
#define A_ST (TILE_M * 128)       // 16 KB / stage
#define B_ST (TILE_N * 128)       // 32 KB / stage
#define TILES_M (BM / TILE_M)     // 64
#define TILES_N (NNN / TILE_N)    // 64
#define SMEM_BYTES (STAGES * (A_ST + B_ST) + 1024)   // 197632 < 227KB

// fp8 operand scratch (allocation-free: device globals)
__device__ __align__(128) unsigned char g_Xq[(size_t)BM  * KKK];   // 32 MB
__device__ __align__(128) unsigned char g_Wq[(size_t)NNN * KKK];   // 64 MB

// ----------------------------------------------------------------------------
// helpers
// ----------------------------------------------------------------------------
static __device__ __forceinline__ uint32_t smem_u32(const void* p) {
    uint32_t a;
    asm("{ .reg .u64 t; cvta.to.shared.u64 t, %1; cvt.u32.u64 %0, t; }"
        : "=r"(a) : "l"(p));
    return a;
}

#define SWZ128(off) ((off) ^ (((off) >> 3) & 0x70))

static __device__ __forceinline__ void cp16(uint32_t saddr, const void* g) {
    asm volatile("cp.async.cg.shared.global [%0], [%1], 16;" :: "r"(saddr), "l"(g));
}

static __device__ __forceinline__ void ldsm_x4(uint32_t* r, uint32_t addr) {
    asm volatile("ldmatrix.sync.aligned.m8n8.x4.shared.b16 {%0,%1,%2,%3}, [%4];"
                 : "=r"(r[0]), "=r"(r[1]), "=r"(r[2]), "=r"(r[3]) : "r"(addr));
}

// fp8 e4m3 MMA, f32 accumulators (exact for +/-1 operands)
#define MMA_FP8(d, a, b0, b1)                                                 \
    asm volatile("mma.sync.aligned.m16n8k32.row.col.f32.e4m3.e4m3.f32 "       \
                 "{%0,%1,%2,%3}, {%4,%5,%6,%7}, {%8,%9}, {%0,%1,%2,%3};"      \
                 : "+f"((d)[0]), "+f"((d)[1]), "+f"((d)[2]), "+f"((d)[3])     \
                 : "r"((a)[0]), "r"((a)[1]), "r"((a)[2]), "r"((a)[3]),        \
                   "r"(b0), "r"(b1))

// ----------------------------------------------------------------------------
// Binarize: f32 -> e4m3 (+1.0 = 0x38, -1.0 = 0xB8)
// ----------------------------------------------------------------------------
__global__ void quant_x_kernel(const float4* __restrict__ x, int n4) {
    int i = blockIdx.x * blockDim.x + threadIdx.x;
    if (i >= n4) return;
    float4 v = x[i];
    uchar4 o;
    o.x = (v.x >= 0.f) ? 0x38 : 0xB8;
    o.y = (v.y >= 0.f) ? 0x38 : 0xB8;
    o.z = (v.z >= 0.f) ? 0x38 : 0xB8;
    o.w = (v.w >= 0.f) ? 0x38 : 0xB8;
    reinterpret_cast<uchar4*>(g_Xq)[i] = o;
}

__global__ void quant_w_kernel(const float4* __restrict__ w,
                               const float* __restrict__ th, int n4) {
    int i = blockIdx.x * blockDim.x + threadIdx.x;
    if (i >= n4) return;
    float t = th[i >> 10];   // 1024 float4 groups per 4096-wide row
    float4 v = w[i];
    uchar4 o;
    o.x = (v.x - t >= 0.f) ? 0x38 : 0xB8;
    o.y = (v.y - t >= 0.f) ? 0x38 : 0xB8;
    o.z = (v.z - t >= 0.f) ? 0x38 : 0xB8;
    o.w = (v.w - t >= 0.f) ? 0x38 : 0xB8;
    reinterpret_cast<uchar4*>(g_Wq)[i] = o;
}

// ----------------------------------------------------------------------------
// GEMM: 128x256 tile / CTA, 256 threads (8 warps, 2x4 grid of 64x64 warp tiles),
// 4-stage cp.async pipeline (one sync per chunk), fp8 m16n8k32 MMA.
// ----------------------------------------------------------------------------
static __device__ __forceinline__ void load_stage(
    uint32_t sA, uint32_t sB,
    const unsigned char* gA, const unsigned char* gB,
    uint32_t kc, uint32_t stage, uint32_t tid)
{
    uint32_t aBase = sA + stage * A_ST;
    uint32_t bBase = sB + stage * B_ST;
    uint32_t koff = kc * 128;                     // bytes: 128 fp8 per chunk
#pragma unroll
    for (uint32_t i = 0; i < 4; i++) {            // A: 128 rows x 128B = 1024 x 16B
        uint32_t li  = i * 256 + tid;
        uint32_t row = li >> 3;
        uint32_t c16 = (li & 7) * 16;
        uint32_t off = row * 128 + c16;
        cp16(aBase + SWZ128(off), gA + (size_t)row * KKK + koff + c16);
    }
#pragma unroll
    for (uint32_t i = 0; i < 8; i++) {            // B: 256 rows x 128B = 2048 x 16B
        uint32_t li  = i * 256 + tid;
        uint32_t row = li >> 3;
        uint32_t c16 = (li & 7) * 16;
        uint32_t off = row * 128 + c16;
        cp16(bBase + SWZ128(off), gB + (size_t)row * KKK + koff + c16);
    }
}

__global__ void __launch_bounds__(256, 1)
bgemm_kernel(float* __restrict__ out, const float* __restrict__ shift) {
    extern __shared__ __align__(128) unsigned char smem[];
    uint32_t base = (smem_u32(smem) + 1023u) & ~1023u;
    uint32_t sA   = base;
    uint32_t sB   = base + STAGES * A_ST;

    uint32_t tid  = threadIdx.x;
    uint32_t wid  = tid >> 5;
    uint32_t lane = tid & 31;
    uint32_t wm   = wid >> 2;       // 0..1  -> m offset wm*64
    uint32_t wn   = wid & 3;        // 0..3  -> n offset wn*64

    // tile swizzle: groups of 4 tn-columns, tm fastest within a group.
    uint32_t idx = blockIdx.x;
    uint32_t tm  = (idx & 255) >> 2;
    uint32_t tn  = ((idx >> 8) << 2) | (idx & 3);

    const unsigned char* gA = g_Xq + (size_t)tm * TILE_M * KKK;
    const unsigned char* gB = g_Wq + (size_t)tn * TILE_N * KKK;

    float acc[4][8][4];                 // 4 m16-tiles x 8 n8-tiles x 4 f32
#pragma unroll
    for (int mt = 0; mt < 4; mt++)
#pragma unroll
        for (int nt = 0; nt < 8; nt++)
#pragma unroll
            for (int j = 0; j < 4; j++) acc[mt][nt][j] = 0.0f;

    // per-lane ldmatrix address components (matrix id = lane>>3)
    // byte-level mapping validated bit-exact by the R7 s8 m16n8k32 kernel
    uint32_t mat = lane >> 3;
    uint32_t a_row_l = (lane & 7) + ((mat & 1) << 3);   // +8 rows for mats 1,3
    uint32_t a_kb_l  = (mat >> 1) << 4;                 // +16 bytes for mats 2,3
    uint32_t b_row_l = (lane & 7) + ((mat >> 1) << 3);  // +8 n-rows for mats 2,3
    uint32_t b_kb_l  = (mat & 1) << 4;                  // +16 bytes for mats 1,3

    // Swizzle CSE: SWZ128(row*128+c) = row*128 + (c ^ ((lane&7)<<4));
    // kseg (32B step) enters via XOR of (kseg<<5) (disjoint bit fields).
    uint32_t swz_mask = (lane & 7) << 4;
    uint32_t a_base_off[4], b_base_off[4];
#pragma unroll
    for (uint32_t mt = 0; mt < 4; mt++)
        a_base_off[mt] = (wm * 64 + mt * 16 + a_row_l) * 128 + (a_kb_l ^ swz_mask);
#pragma unroll
    for (uint32_t bt = 0; bt < 4; bt++)
        b_base_off[bt] = (wn * 64 + bt * 16 + b_row_l) * 128 + (b_kb_l ^ swz_mask);

    // prologue: chunks 0,1 into stages 0,1
    load_stage(sA, sB, gA, gB, 0, 0, tid);
    asm volatile("cp.async.commit_group;" ::: "memory");
    load_stage(sA, sB, gA, gB, 1, 1, tid);
    asm volatile("cp.async.commit_group;" ::: "memory");

#pragma unroll 1
    for (uint32_t kc = 0; kc < NKC; kc++) {
        // prefetch chunk kc+2 into stage (kc+2)&3 (disjoint from readable stages)
        if (kc + 2 < NKC)
            load_stage(sA, sB, gA, gB, kc + 2, (kc + 2) & 3, tid);
        asm volatile("cp.async.commit_group;" ::: "memory");
        asm volatile("cp.async.wait_group 2;" ::: "memory");
        __syncthreads();

        uint32_t aBase = sA + (kc & 3) * A_ST;
        uint32_t bBase = sB + (kc & 3) * B_ST;

#pragma unroll
        for (int kseg = 0; kseg < 4; kseg++) {     // 4 x k32 (32B) per 128B chunk
            uint32_t kx = (uint32_t)(kseg << 5);
            uint32_t afr[4][4], bfr[4][4];
#pragma unroll
            for (int mt = 0; mt < 4; mt++)
                ldsm_x4(afr[mt], aBase + (a_base_off[mt] ^ kx));
#pragma unroll
            for (int bt = 0; bt < 4; bt++)
                ldsm_x4(bfr[bt], bBase + (b_base_off[bt] ^ kx));
#pragma unroll
            for (int mt = 0; mt < 4; mt++)
#pragma unroll
                for (int nt = 0; nt < 8; nt++) {
                    uint32_t* b = &bfr[nt >> 1][(nt & 1) * 2];
                    MMA_FP8(acc[mt][nt], afr[mt], b[0], b[1]);
                }
        }
        // no trailing sync: 4-stage ring guarantees no WAR on in-flight stages
    }

    // epilogue: scale + store (exact: integer-valued f32 * power-of-two)
    float sp = *shift;
    float scale = exp2f(rintf(fminf(fmaxf(sp, -8.0f), 0.0f)));

    uint32_t row_l = lane >> 2;
    uint32_t col_l = (lane & 3) * 2;
#pragma unroll
    for (int mt = 0; mt < 4; mt++) {
        size_t mg0 = (size_t)(tm * TILE_M + wm * 64 + mt * 16 + row_l);
        float* o0 = out + mg0 * NNN;
        float* o1 = o0 + 8 * (size_t)NNN;
#pragma unroll
        for (int nt = 0; nt < 8; nt++) {
            uint32_t ng = tn * TILE_N + wn * 64 + nt * 8 + col_l;
            float2 v0, v1;
            v0.x = acc[mt][nt][0] * scale;
            v0.y = acc[mt][nt][1] * scale;
            v1.x = acc[mt][nt][2] * scale;
            v1.y = acc[mt][nt][3] * scale;
            *reinterpret_cast<float2*>(o0 + ng) = v0;
            *reinterpret_cast<float2*>(o1 + ng) = v1;
        }
    }
}

// ----------------------------------------------------------------------------
// launch
// ----------------------------------------------------------------------------
extern "C" void kernel_launch(void* const* d_in, const int* in_sizes, int n_in,
                              void* d_out, int out_size) {
    (void)in_sizes; (void)n_in; (void)out_size;
    const float* x  = (const float*)d_in[0];   // [4,2048,4096]
    const float* w  = (const float*)d_in[1];   // [16384,4096]
    const float* th = (const float*)d_in[2];   // [16384,1]
    const float* sh = (const float*)d_in[3];   // scalar
    float* out = (float*)d_out;                // [4,2048,16384]

    int nx4 = (BM * KKK) / 4;
    int nw4 = (NNN * KKK) / 4;
    quant_x_kernel<<<(nx4 + 255) / 256, 256>>>((const float4*)x, nx4);
    quant_w_kernel<<<(nw4 + 255) / 256, 256>>>((const float4*)w, th, nw4);

    cudaFuncSetAttribute(bgemm_kernel,
                         cudaFuncAttributeMaxDynamicSharedMemorySize, SMEM_BYTES);
    bgemm_kernel<<<TILES_M * TILES_N, 256, SMEM_BYTES>>>(out, sh);
}

// round 15
// speedup vs baseline: 1.1097x; 1.1097x over previous
#include <cuda_runtime.h>
#include <cuda_bf16.h>
#include <cstdint>
#include <cmath>

// ============================================================================
// out[m,n] = sum_k sign(x[m,k]) * sign(w[n,k]-th[n]) * 2^round(clip(shift,-8,0))
//   M = 8192, N = 16384, K = 4096, out fp32.
// Best legacy path (R7-R14 sweep): mma.sync m16n8k16.f32.bf16.bf16.f32, rt~8/SMSP.
// R12 = 2362us with ~19% overhead above the 1.9ms issue floor. This round:
// two chunks per barrier (32 serial sections instead of 64), 8-kseg
// software-pipelined body with LDSM/MMA interleave across the chunk boundary.
// ============================================================================

#define BM   8192
#define NNN  16384
#define KKK  4096
#define TILE_M 128
#define TILE_N 256
#define NKC  (KKK / 64)           // 64 k-chunks of 64 bf16 (=128B SW128 row)
#define STAGES 4
#define A_ST (TILE_M * 128)       // 16 KB / stage
#define B_ST (TILE_N * 128)       // 32 KB / stage
#define TILES_M (BM / TILE_M)     // 64
#define TILES_N (NNN / TILE_N)    // 64
#define SMEM_BYTES (STAGES * (A_ST + B_ST) + 1024)   // 197632 < 227KB

// bf16 operand scratch (allocation-free: device globals)
__device__ __align__(128) unsigned char g_Xq[(size_t)BM  * KKK * 2];   // 64 MB
__device__ __align__(128) unsigned char g_Wq[(size_t)NNN * KKK * 2];   // 128 MB

// ----------------------------------------------------------------------------
// helpers
// ----------------------------------------------------------------------------
static __device__ __forceinline__ uint32_t smem_u32(const void* p) {
    uint32_t a;
    asm("{ .reg .u64 t; cvta.to.shared.u64 t, %1; cvt.u32.u64 %0, t; }"
        : "=r"(a) : "l"(p));
    return a;
}

#define SWZ128(off) ((off) ^ (((off) >> 3) & 0x70))

static __device__ __forceinline__ void cp16(uint32_t saddr, const void* g) {
    asm volatile("cp.async.cg.shared.global [%0], [%1], 16;" :: "r"(saddr), "l"(g));
}

static __device__ __forceinline__ void ldsm_x4(uint32_t* r, uint32_t addr) {
    asm volatile("ldmatrix.sync.aligned.m8n8.x4.shared.b16 {%0,%1,%2,%3}, [%4];"
                 : "=r"(r[0]), "=r"(r[1]), "=r"(r[2]), "=r"(r[3]) : "r"(addr));
}

// bf16 HMMA, f32 accumulators (exact for +/-1 operands, K <= 2^24)
#define MMA_BF16(d, a, b0, b1)                                                \
    asm volatile("mma.sync.aligned.m16n8k16.row.col.f32.bf16.bf16.f32 "       \
                 "{%0,%1,%2,%3}, {%4,%5,%6,%7}, {%8,%9}, {%0,%1,%2,%3};"      \
                 : "+f"((d)[0]), "+f"((d)[1]), "+f"((d)[2]), "+f"((d)[3])     \
                 : "r"((a)[0]), "r"((a)[1]), "r"((a)[2]), "r"((a)[3]),        \
                   "r"(b0), "r"(b1))

// one mt-row of 8 n8-tiles
#define MMA_ROW(mt, cur)                                                      \
    _Pragma("unroll")                                                         \
    for (int nt = 0; nt < 8; nt++) {                                          \
        uint32_t* b = &bfr[cur][nt >> 1][(nt & 1) * 2];                       \
        MMA_BF16(acc[mt][nt], afr[cur][mt], b[0], b[1]);                      \
    }

// ----------------------------------------------------------------------------
// Binarize: f32 -> bf16 (+1.0 = 0x3F80, -1.0 = 0xBF80)
// ----------------------------------------------------------------------------
__global__ void quant_x_kernel(const float4* __restrict__ x, int n4) {
    int i = blockIdx.x * blockDim.x + threadIdx.x;
    if (i >= n4) return;
    float4 v = x[i];
    ushort4 o;
    o.x = (v.x >= 0.f) ? 0x3F80 : 0xBF80;
    o.y = (v.y >= 0.f) ? 0x3F80 : 0xBF80;
    o.z = (v.z >= 0.f) ? 0x3F80 : 0xBF80;
    o.w = (v.w >= 0.f) ? 0x3F80 : 0xBF80;
    reinterpret_cast<ushort4*>(g_Xq)[i] = o;
}

__global__ void quant_w_kernel(const float4* __restrict__ w,
                               const float* __restrict__ th, int n4) {
    int i = blockIdx.x * blockDim.x + threadIdx.x;
    if (i >= n4) return;
    float t = th[i >> 10];   // 1024 float4 per 4096-wide row
    float4 v = w[i];
    ushort4 o;
    o.x = (v.x - t >= 0.f) ? 0x3F80 : 0xBF80;
    o.y = (v.y - t >= 0.f) ? 0x3F80 : 0xBF80;
    o.z = (v.z - t >= 0.f) ? 0x3F80 : 0xBF80;
    o.w = (v.w - t >= 0.f) ? 0x3F80 : 0xBF80;
    reinterpret_cast<ushort4*>(g_Wq)[i] = o;
}

// ----------------------------------------------------------------------------
// GEMM: 128x256 tile / CTA, 256 threads (8 warps, 2x4 grid of 64x64 warp tiles),
// 4-stage cp.async ring, TWO chunks per barrier, 8-kseg pipelined body.
// ----------------------------------------------------------------------------
static __device__ __forceinline__ void load_stage(
    uint32_t sA, uint32_t sB,
    const unsigned char* gA, const unsigned char* gB,
    uint32_t kc, uint32_t stage, uint32_t tid)
{
    uint32_t aBase = sA + stage * A_ST;
    uint32_t bBase = sB + stage * B_ST;
    uint32_t koff = kc * 128;                     // bytes: 64 bf16 per chunk
#pragma unroll
    for (uint32_t i = 0; i < 4; i++) {            // A: 128 rows x 128B = 1024 x 16B
        uint32_t li  = i * 256 + tid;
        uint32_t row = li >> 3;
        uint32_t c16 = (li & 7) * 16;
        uint32_t off = row * 128 + c16;
        cp16(aBase + SWZ128(off), gA + (size_t)row * (KKK * 2) + koff + c16);
    }
#pragma unroll
    for (uint32_t i = 0; i < 8; i++) {            // B: 256 rows x 128B = 2048 x 16B
        uint32_t li  = i * 256 + tid;
        uint32_t row = li >> 3;
        uint32_t c16 = (li & 7) * 16;
        uint32_t off = row * 128 + c16;
        cp16(bBase + SWZ128(off), gB + (size_t)row * (KKK * 2) + koff + c16);
    }
}

__global__ void __launch_bounds__(256, 1)
bgemm_kernel(float* __restrict__ out, const float* __restrict__ shift) {
    extern __shared__ __align__(128) unsigned char smem[];
    uint32_t base = (smem_u32(smem) + 1023u) & ~1023u;
    uint32_t sA   = base;
    uint32_t sB   = base + STAGES * A_ST;

    uint32_t tid  = threadIdx.x;
    uint32_t wid  = tid >> 5;
    uint32_t lane = tid & 31;
    uint32_t wm   = wid >> 2;       // 0..1  -> m offset wm*64
    uint32_t wn   = wid & 3;        // 0..3  -> n offset wn*64

    // tile swizzle: groups of 4 tn-columns, tm fastest within a group.
    uint32_t idx = blockIdx.x;
    uint32_t tm  = (idx & 255) >> 2;
    uint32_t tn  = ((idx >> 8) << 2) | (idx & 3);

    const unsigned char* gA = g_Xq + (size_t)tm * TILE_M * (KKK * 2);
    const unsigned char* gB = g_Wq + (size_t)tn * TILE_N * (KKK * 2);

    float acc[4][8][4];                 // 4 m16-tiles x 8 n8-tiles x 4 f32
#pragma unroll
    for (int mt = 0; mt < 4; mt++)
#pragma unroll
        for (int nt = 0; nt < 8; nt++)
#pragma unroll
            for (int j = 0; j < 4; j++) acc[mt][nt][j] = 0.0f;

    // per-lane ldmatrix address components (matrix id = lane>>3)
    uint32_t mat = lane >> 3;
    uint32_t a_row_l = (lane & 7) + ((mat & 1) << 3);
    uint32_t a_kb_l  = (mat >> 1) << 4;
    uint32_t b_row_l = (lane & 7) + ((mat >> 1) << 3);
    uint32_t b_kb_l  = (mat & 1) << 4;

    // Swizzle CSE: SWZ128(row*128+c) = row*128 + (c ^ ((lane&7)<<4));
    // kseg enters via XOR of ((kseg&3)<<5) (disjoint bit fields).
    uint32_t swz_mask = (lane & 7) << 4;
    uint32_t a_base_off[4], b_base_off[4];
#pragma unroll
    for (uint32_t mt = 0; mt < 4; mt++)
        a_base_off[mt] = (wm * 64 + mt * 16 + a_row_l) * 128 + (a_kb_l ^ swz_mask);
#pragma unroll
    for (uint32_t bt = 0; bt < 4; bt++)
        b_base_off[bt] = (wn * 64 + bt * 16 + b_row_l) * 128 + (b_kb_l ^ swz_mask);

    // prologue: chunks 0,1 into stages 0,1 as ONE commit group
    load_stage(sA, sB, gA, gB, 0, 0, tid);
    load_stage(sA, sB, gA, gB, 1, 1, tid);
    asm volatile("cp.async.commit_group;" ::: "memory");

#pragma unroll 1
    for (uint32_t kc2 = 0; kc2 < NKC; kc2 += 2) {
        // chunks kc2,kc2+1 were committed one iteration ago -> landed by now
        asm volatile("cp.async.wait_group 0;" ::: "memory");
        __syncthreads();
        // refill stages (kc2+2)&3,(kc2+3)&3 == (kc2-2)&3,(kc2-1)&3 -- all warps
        // are past them (they computed those chunks before this barrier).
        if (kc2 + 2 < NKC) {
            load_stage(sA, sB, gA, gB, kc2 + 2, (kc2 + 2) & 3, tid);
            load_stage(sA, sB, gA, gB, kc2 + 3, (kc2 + 3) & 3, tid);
            asm volatile("cp.async.commit_group;" ::: "memory");
        }

        // 2-chunk straight-line body: 8 ksegs, LDSM pipelined one kseg ahead
        uint32_t aBs[2] = { sA + (kc2 & 3) * A_ST, sA + ((kc2 + 1) & 3) * A_ST };
        uint32_t bBs[2] = { sB + (kc2 & 3) * B_ST, sB + ((kc2 + 1) & 3) * B_ST };

        uint32_t afr[2][4][4], bfr[2][4][4];
#pragma unroll
        for (int mt = 0; mt < 4; mt++)
            ldsm_x4(afr[0][mt], aBs[0] + a_base_off[mt]);
#pragma unroll
        for (int bt = 0; bt < 4; bt++)
            ldsm_x4(bfr[0][bt], bBs[0] + b_base_off[bt]);

#pragma unroll
        for (int kseg = 0; kseg < 8; kseg++) {
            int cur = kseg & 1;
            int nxt = cur ^ 1;
            int ns  = (kseg + 1) >> 2;                       // stage of kseg+1
            uint32_t kx = (uint32_t)(((kseg + 1) & 3) << 5); // 32B step in stage
            if (kseg < 7) { ldsm_x4(afr[nxt][0], aBs[ns] + (a_base_off[0] ^ kx));
                            ldsm_x4(afr[nxt][1], aBs[ns] + (a_base_off[1] ^ kx)); }
            MMA_ROW(0, cur)
            if (kseg < 7) { ldsm_x4(afr[nxt][2], aBs[ns] + (a_base_off[2] ^ kx));
                            ldsm_x4(afr[nxt][3], aBs[ns] + (a_base_off[3] ^ kx)); }
            MMA_ROW(1, cur)
            if (kseg < 7) { ldsm_x4(bfr[nxt][0], bBs[ns] + (b_base_off[0] ^ kx));
                            ldsm_x4(bfr[nxt][1], bBs[ns] + (b_base_off[1] ^ kx)); }
            MMA_ROW(2, cur)
            if (kseg < 7) { ldsm_x4(bfr[nxt][2], bBs[ns] + (b_base_off[2] ^ kx));
                            ldsm_x4(bfr[nxt][3], bBs[ns] + (b_base_off[3] ^ kx)); }
            MMA_ROW(3, cur)
        }
        // no trailing sync: next iteration's barrier precedes any stage reuse
    }

    // epilogue: scale + store (exact: integer-valued f32 * power-of-two)
    float sp = *shift;
    float scale = exp2f(rintf(fminf(fmaxf(sp, -8.0f), 0.0f)));

    uint32_t row_l = lane >> 2;
    uint32_t col_l = (lane & 3) * 2;
#pragma unroll
    for (int mt = 0; mt < 4; mt++) {
        size_t mg0 = (size_t)(tm * TILE_M + wm * 64 + mt * 16 + row_l);
        float* o0 = out + mg0 * NNN;
        float* o1 = o0 + 8 * (size_t)NNN;
#pragma unroll
        for (int nt = 0; nt < 8; nt++) {
            uint32_t ng = tn * TILE_N + wn * 64 + nt * 8 + col_l;
            float2 v0, v1;
            v0.x = acc[mt][nt][0] * scale;
            v0.y = acc[mt][nt][1] * scale;
            v1.x = acc[mt][nt][2] * scale;
            v1.y = acc[mt][nt][3] * scale;
            *reinterpret_cast<float2*>(o0 + ng) = v0;
            *reinterpret_cast<float2*>(o1 + ng) = v1;
        }
    }
}

// ----------------------------------------------------------------------------
// launch
// ----------------------------------------------------------------------------
extern "C" void kernel_launch(void* const* d_in, const int* in_sizes, int n_in,
                              void* d_out, int out_size) {
    (void)in_sizes; (void)n_in; (void)out_size;
    const float* x  = (const float*)d_in[0];   // [4,2048,4096]
    const float* w  = (const float*)d_in[1];   // [16384,4096]
    const float* th = (const float*)d_in[2];   // [16384,1]
    const float* sh = (const float*)d_in[3];   // scalar
    float* out = (float*)d_out;                // [4,2048,16384]

    int nx4 = (BM * KKK) / 4;
    int nw4 = (NNN * KKK) / 4;
    quant_x_kernel<<<(nx4 + 255) / 256, 256>>>((const float4*)x, nx4);
    quant_w_kernel<<<(nw4 + 255) / 256, 256>>>((const float4*)w, th, nw4);

    cudaFuncSetAttribute(bgemm_kernel,
                         cudaFuncAttributeMaxDynamicSharedMemorySize, SMEM_BYTES);
    bgemm_kernel<<<TILES_M * TILES_N, 256, SMEM_BYTES>>>(out, sh);
}

// round 16
// speedup vs baseline: 1.1555x; 1.0413x over previous
#include <cuda_runtime.h>
#include <cuda_bf16.h>
#include <cstdint>
#include <cmath>

// ============================================================================
// out[m,n] = sum_k sign(x[m,k]) * sign(w[n,k]-th[n]) * 2^round(clip(shift,-8,0))
//   M = 8192, N = 16384, K = 4096, out fp32.
// Legacy bf16 HMMA m16n8k16 (rt~8/SMSP) -> per-SMSP issue floor 2048 cyc/chunk.
// R12 (2 warps/SMSP) = 18% above floor: stalls idle the tensor pipe.
// This round: 512 threads (16 warps, 4/SMSP), warp tile 32x64, same 128x256 CTA
// tile and R12 pipeline shape. More warps/scheduler -> fill MMA issue slots.
// ============================================================================

#define BM   8192
#define NNN  16384
#define KKK  4096
#define TILE_M 128
#define TILE_N 256
#define NKC  (KKK / 64)           // 64 k-chunks of 64 bf16 (=128B SW128 row)
#define STAGES 4
#define A_ST (TILE_M * 128)       // 16 KB / stage
#define B_ST (TILE_N * 128)       // 32 KB / stage
#define TILES_M (BM / TILE_M)     // 64
#define TILES_N (NNN / TILE_N)    // 64
#define SMEM_BYTES (STAGES * (A_ST + B_ST) + 1024)   // 197632 < 227KB
#define THREADS 512

// bf16 operand scratch (allocation-free: device globals)
__device__ __align__(128) unsigned char g_Xq[(size_t)BM  * KKK * 2];   // 64 MB
__device__ __align__(128) unsigned char g_Wq[(size_t)NNN * KKK * 2];   // 128 MB

// ----------------------------------------------------------------------------
// helpers
// ----------------------------------------------------------------------------
static __device__ __forceinline__ uint32_t smem_u32(const void* p) {
    uint32_t a;
    asm("{ .reg .u64 t; cvta.to.shared.u64 t, %1; cvt.u32.u64 %0, t; }"
        : "=r"(a) : "l"(p));
    return a;
}

#define SWZ128(off) ((off) ^ (((off) >> 3) & 0x70))

static __device__ __forceinline__ void cp16(uint32_t saddr, const void* g) {
    asm volatile("cp.async.cg.shared.global [%0], [%1], 16;" :: "r"(saddr), "l"(g));
}

static __device__ __forceinline__ void ldsm_x4(uint32_t* r, uint32_t addr) {
    asm volatile("ldmatrix.sync.aligned.m8n8.x4.shared.b16 {%0,%1,%2,%3}, [%4];"
                 : "=r"(r[0]), "=r"(r[1]), "=r"(r[2]), "=r"(r[3]) : "r"(addr));
}

// bf16 HMMA, f32 accumulators (exact for +/-1 operands, K <= 2^24)
#define MMA_BF16(d, a, b0, b1)                                                \
    asm volatile("mma.sync.aligned.m16n8k16.row.col.f32.bf16.bf16.f32 "       \
                 "{%0,%1,%2,%3}, {%4,%5,%6,%7}, {%8,%9}, {%0,%1,%2,%3};"      \
                 : "+f"((d)[0]), "+f"((d)[1]), "+f"((d)[2]), "+f"((d)[3])     \
                 : "r"((a)[0]), "r"((a)[1]), "r"((a)[2]), "r"((a)[3]),        \
                   "r"(b0), "r"(b1))

// ----------------------------------------------------------------------------
// Binarize: f32 -> bf16 (+1.0 = 0x3F80, -1.0 = 0xBF80)
// ----------------------------------------------------------------------------
__global__ void quant_x_kernel(const float4* __restrict__ x, int n4) {
    int i = blockIdx.x * blockDim.x + threadIdx.x;
    if (i >= n4) return;
    float4 v = x[i];
    ushort4 o;
    o.x = (v.x >= 0.f) ? 0x3F80 : 0xBF80;
    o.y = (v.y >= 0.f) ? 0x3F80 : 0xBF80;
    o.z = (v.z >= 0.f) ? 0x3F80 : 0xBF80;
    o.w = (v.w >= 0.f) ? 0x3F80 : 0xBF80;
    reinterpret_cast<ushort4*>(g_Xq)[i] = o;
}

__global__ void quant_w_kernel(const float4* __restrict__ w,
                               const float* __restrict__ th, int n4) {
    int i = blockIdx.x * blockDim.x + threadIdx.x;
    if (i >= n4) return;
    float t = th[i >> 10];   // 1024 float4 per 4096-wide row
    float4 v = w[i];
    ushort4 o;
    o.x = (v.x - t >= 0.f) ? 0x3F80 : 0xBF80;
    o.y = (v.y - t >= 0.f) ? 0x3F80 : 0xBF80;
    o.z = (v.z - t >= 0.f) ? 0x3F80 : 0xBF80;
    o.w = (v.w - t >= 0.f) ? 0x3F80 : 0xBF80;
    reinterpret_cast<ushort4*>(g_Wq)[i] = o;
}

// ----------------------------------------------------------------------------
// GEMM: 128x256 tile / CTA, 512 threads (16 warps, 4x4 grid of 32x64 warp tiles),
// 4-stage cp.async pipeline, one barrier per chunk (R12 shape).
// ----------------------------------------------------------------------------
static __device__ __forceinline__ void load_stage(
    uint32_t sA, uint32_t sB,
    const unsigned char* gA, const unsigned char* gB,
    uint32_t kc, uint32_t stage, uint32_t tid)
{
    uint32_t aBase = sA + stage * A_ST;
    uint32_t bBase = sB + stage * B_ST;
    uint32_t koff = kc * 128;                     // bytes: 64 bf16 per chunk
#pragma unroll
    for (uint32_t i = 0; i < 2; i++) {            // A: 128 rows x 128B = 1024 x 16B
        uint32_t li  = i * 512 + tid;
        uint32_t row = li >> 3;
        uint32_t c16 = (li & 7) * 16;
        uint32_t off = row * 128 + c16;
        cp16(aBase + SWZ128(off), gA + (size_t)row * (KKK * 2) + koff + c16);
    }
#pragma unroll
    for (uint32_t i = 0; i < 4; i++) {            // B: 256 rows x 128B = 2048 x 16B
        uint32_t li  = i * 512 + tid;
        uint32_t row = li >> 3;
        uint32_t c16 = (li & 7) * 16;
        uint32_t off = row * 128 + c16;
        cp16(bBase + SWZ128(off), gB + (size_t)row * (KKK * 2) + koff + c16);
    }
}

__global__ void __launch_bounds__(THREADS, 1)
bgemm_kernel(float* __restrict__ out, const float* __restrict__ shift) {
    extern __shared__ __align__(128) unsigned char smem[];
    uint32_t base = (smem_u32(smem) + 1023u) & ~1023u;
    uint32_t sA   = base;
    uint32_t sB   = base + STAGES * A_ST;

    uint32_t tid  = threadIdx.x;
    uint32_t wid  = tid >> 5;
    uint32_t lane = tid & 31;
    uint32_t wm   = wid & 3;        // 0..3  -> m offset wm*32
    uint32_t wn   = wid >> 2;       // 0..3  -> n offset wn*64

    // tile swizzle: groups of 4 tn-columns, tm fastest within a group.
    uint32_t idx = blockIdx.x;
    uint32_t tm  = (idx & 255) >> 2;
    uint32_t tn  = ((idx >> 8) << 2) | (idx & 3);

    const unsigned char* gA = g_Xq + (size_t)tm * TILE_M * (KKK * 2);
    const unsigned char* gB = g_Wq + (size_t)tn * TILE_N * (KKK * 2);

    float acc[2][8][4];                 // 2 m16-tiles x 8 n8-tiles x 4 f32
#pragma unroll
    for (int mt = 0; mt < 2; mt++)
#pragma unroll
        for (int nt = 0; nt < 8; nt++)
#pragma unroll
            for (int j = 0; j < 4; j++) acc[mt][nt][j] = 0.0f;

    // per-lane ldmatrix address components (matrix id = lane>>3)
    uint32_t mat = lane >> 3;
    uint32_t a_row_l = (lane & 7) + ((mat & 1) << 3);
    uint32_t a_kb_l  = (mat >> 1) << 4;
    uint32_t b_row_l = (lane & 7) + ((mat >> 1) << 3);
    uint32_t b_kb_l  = (mat & 1) << 4;

    // Swizzle CSE: SWZ128(row*128+c) = row*128 + (c ^ ((lane&7)<<4));
    // kseg enters via XOR of (kseg<<5) (disjoint bit fields).
    uint32_t swz_mask = (lane & 7) << 4;
    uint32_t a_base_off[2], b_base_off[4];
#pragma unroll
    for (uint32_t mt = 0; mt < 2; mt++)
        a_base_off[mt] = (wm * 32 + mt * 16 + a_row_l) * 128 + (a_kb_l ^ swz_mask);
#pragma unroll
    for (uint32_t bt = 0; bt < 4; bt++)
        b_base_off[bt] = (wn * 64 + bt * 16 + b_row_l) * 128 + (b_kb_l ^ swz_mask);

    // prologue: chunks 0,1 into stages 0,1
    load_stage(sA, sB, gA, gB, 0, 0, tid);
    asm volatile("cp.async.commit_group;" ::: "memory");
    load_stage(sA, sB, gA, gB, 1, 1, tid);
    asm volatile("cp.async.commit_group;" ::: "memory");

#pragma unroll 1
    for (uint32_t kc = 0; kc < NKC; kc++) {
        // prefetch chunk kc+2 into stage (kc+2)&3 (disjoint from readable stages)
        if (kc + 2 < NKC)
            load_stage(sA, sB, gA, gB, kc + 2, (kc + 2) & 3, tid);
        asm volatile("cp.async.commit_group;" ::: "memory");
        asm volatile("cp.async.wait_group 2;" ::: "memory");
        __syncthreads();

        uint32_t aBase = sA + (kc & 3) * A_ST;
        uint32_t bBase = sB + (kc & 3) * B_ST;

#pragma unroll
        for (int kseg = 0; kseg < 4; kseg++) {
            uint32_t kx = (uint32_t)(kseg << 5);
            uint32_t afr[2][4], bfr[4][4];
#pragma unroll
            for (int mt = 0; mt < 2; mt++)
                ldsm_x4(afr[mt], aBase + (a_base_off[mt] ^ kx));
#pragma unroll
            for (int bt = 0; bt < 4; bt++)
                ldsm_x4(bfr[bt], bBase + (b_base_off[bt] ^ kx));
#pragma unroll
            for (int mt = 0; mt < 2; mt++)
#pragma unroll
                for (int nt = 0; nt < 8; nt++) {
                    uint32_t* b = &bfr[nt >> 1][(nt & 1) * 2];
                    MMA_BF16(acc[mt][nt], afr[mt], b[0], b[1]);
                }
        }
        // no trailing sync: 4-stage ring guarantees no WAR on in-flight stages
    }

    // epilogue: scale + store (exact: integer-valued f32 * power-of-two)
    float sp = *shift;
    float scale = exp2f(rintf(fminf(fmaxf(sp, -8.0f), 0.0f)));

    uint32_t row_l = lane >> 2;
    uint32_t col_l = (lane & 3) * 2;
#pragma unroll
    for (int mt = 0; mt < 2; mt++) {
        size_t mg0 = (size_t)(tm * TILE_M + wm * 32 + mt * 16 + row_l);
        float* o0 = out + mg0 * NNN;
        float* o1 = o0 + 8 * (size_t)NNN;
#pragma unroll
        for (int nt = 0; nt < 8; nt++) {
            uint32_t ng = tn * TILE_N + wn * 64 + nt * 8 + col_l;
            float2 v0, v1;
            v0.x = acc[mt][nt][0] * scale;
            v0.y = acc[mt][nt][1] * scale;
            v1.x = acc[mt][nt][2] * scale;
            v1.y = acc[mt][nt][3] * scale;
            *reinterpret_cast<float2*>(o0 + ng) = v0;
            *reinterpret_cast<float2*>(o1 + ng) = v1;
        }
    }
}

// ----------------------------------------------------------------------------
// launch
// ----------------------------------------------------------------------------
extern "C" void kernel_launch(void* const* d_in, const int* in_sizes, int n_in,
                              void* d_out, int out_size) {
    (void)in_sizes; (void)n_in; (void)out_size;
    const float* x  = (const float*)d_in[0];   // [4,2048,4096]
    const float* w  = (const float*)d_in[1];   // [16384,4096]
    const float* th = (const float*)d_in[2];   // [16384,1]
    const float* sh = (const float*)d_in[3];   // scalar
    float* out = (float*)d_out;                // [4,2048,16384]

    int nx4 = (BM * KKK) / 4;
    int nw4 = (NNN * KKK) / 4;
    quant_x_kernel<<<(nx4 + 255) / 256, 256>>>((const float4*)x, nx4);
    quant_w_kernel<<<(nw4 + 255) / 256, 256>>>((const float4*)w, th, nw4);

    cudaFuncSetAttribute(bgemm_kernel,
                         cudaFuncAttributeMaxDynamicSharedMemorySize, SMEM_BYTES);
    bgemm_kernel<<<TILES_M * TILES_N, THREADS, SMEM_BYTES>>>(out, sh);
}